// round 13
// baseline (speedup 1.0000x reference)
#include <cuda_runtime.h>

#define Tt 512
#define Dd 1024
#define Ee 64
#define II 512
#define KK 4
#define NPAIR (Tt*KK)

typedef unsigned u32;
typedef unsigned short u16;
typedef unsigned long long u64;

// ---- scratch ----
__device__ int   g_cnt[Ee];
__device__ int   g_slot[Ee*Tt];
__device__ float g_topw[NPAIR];
__device__ u16   g_xh[Tt*Dd];
__device__ u16   g_xl[Tt*Dd];
__device__ u16   g_Hh[NPAIR*II];
__device__ u16   g_Hl[NPAIR*II];
__device__ float g_Y[NPAIR*Dd];

// ---- pipeline geometry ----
#define KC 64                  // k per chunk
#define STG 4
#define ARS 272                // A row stride bytes (256B data + 16 pad)
#define A_SZ (128*ARS)         // 34816
#define XRS 144                // X row stride bytes (128B data + 16 pad)
#define X_SZ (64*XRS)          // 9216
#define STAGE (A_SZ + 2*X_SZ)  // 53248
#define SMEMT (STG*STAGE)      // 212992
#define TXB 49152u             // bytes per chunk
#define USTR 65

__device__ __forceinline__ void cvt_hl(float vx, float vy, u32& h, u32& l){
  asm("cvt.rn.bf16x2.f32 %0, %1, %2;" : "=r"(h) : "f"(vy), "f"(vx));
  float r0 = vx - __uint_as_float(h << 16);
  float r1 = vy - __uint_as_float(h & 0xFFFF0000u);
  asm("cvt.rn.bf16x2.f32 %0, %1, %2;" : "=r"(l) : "f"(r1), "f"(r0));
}

__device__ __forceinline__ void mma16816(float* c, const u32* a, u32 b0, u32 b1){
  asm volatile(
    "mma.sync.aligned.m16n8k16.row.col.f32.bf16.bf16.f32 "
    "{%0,%1,%2,%3}, {%4,%5,%6,%7}, {%8,%9}, {%0,%1,%2,%3};"
    : "+f"(c[0]), "+f"(c[1]), "+f"(c[2]), "+f"(c[3])
    : "r"(a[0]), "r"(a[1]), "r"(a[2]), "r"(a[3]), "r"(b0), "r"(b1));
}

__device__ __forceinline__ void ldsm4(u32* r, u32 addr){
  asm volatile("ldmatrix.sync.aligned.m8n8.x4.shared.b16 {%0,%1,%2,%3}, [%4];"
    : "=r"(r[0]), "=r"(r[1]), "=r"(r[2]), "=r"(r[3]) : "r"(addr));
}

__device__ __forceinline__ float2 lds64f(u32 a){
  float2 v; asm volatile("ld.shared.v2.f32 {%0,%1}, [%2];" : "=f"(v.x), "=f"(v.y) : "r"(a));
  return v;
}

__device__ __forceinline__ void bulk_ld(u32 dst, const void* src, u32 bytes, u32 mbar){
  asm volatile(
    "cp.async.bulk.shared::cluster.global.mbarrier::complete_tx::bytes [%0], [%1], %2, [%3];"
    :: "r"(dst), "l"(src), "r"(bytes), "r"(mbar) : "memory");
}

__device__ __forceinline__ void mb_expect(u32 mbar, u32 tx){
  asm volatile("mbarrier.arrive.expect_tx.shared.b64 _, [%0], %1;" :: "r"(mbar), "r"(tx) : "memory");
}

__device__ __forceinline__ void mb_wait(u32 mbar, u32 parity){
  asm volatile(
    "{\n\t.reg .pred P1;\n\t"
    "WL%=:\n\t"
    "mbarrier.try_wait.parity.acquire.cta.shared::cta.b64 P1, [%0], %1, 0x989680;\n\t"
    "@P1 bra WD%=;\n\t"
    "bra WL%=;\n\t"
    "WD%=:\n\t}"
    :: "r"(mbar), "r"(parity) : "memory");
}

// A fragment pair (hi/lo) from fp32 smem tile (row 256B data, ARS stride)
__device__ __forceinline__ void afrag(u32 Ast, int wid, int lane, int ks, u32* ah, u32* al){
  int gid = lane >> 2, tig = lane & 3;
  u32 a0 = Ast + (u32)(wid*16 + gid)*ARS + (u32)(ks*16 + tig*2)*4;
  float2 v00 = lds64f(a0);
  float2 v10 = lds64f(a0 + 8*ARS);
  float2 v01 = lds64f(a0 + 32);
  float2 v11 = lds64f(a0 + 8*ARS + 32);
  cvt_hl(v00.x, v00.y, ah[0], al[0]);
  cvt_hl(v10.x, v10.y, ah[1], al[1]);
  cvt_hl(v01.x, v01.y, ah[2], al[2]);
  cvt_hl(v11.x, v11.y, ah[3], al[3]);
}

// consume one staged KC=64 chunk: 4 k16 steps
__device__ __forceinline__ void consume(float C[8][4], u32 stg, int wid, int lane, int jpairs){
  u32 Ast = stg, Xh = stg + A_SZ, Xl = Xh + X_SZ;
  int q = lane >> 3, rr = lane & 7;
  u32 bbase = (u32)(((q >> 1) << 3) + rr)*XRS + (q & 1)*16;
  #pragma unroll
  for (int ks = 0; ks < 4; ks++){
    u32 ah[4], al[4];
    afrag(Ast, wid, lane, ks, ah, al);
    #pragma unroll
    for (int jp = 0; jp < 4; jp++){
      if (jp >= jpairs) break;
      u32 bh[4], bl[4];
      ldsm4(bh, Xh + bbase + (u32)(jp*16)*XRS + ks*32);
      ldsm4(bl, Xl + bbase + (u32)(jp*16)*XRS + ks*32);
      int j0 = jp*2, j1 = jp*2 + 1;
      mma16816(C[j0], ah, bh[0], bh[1]);
      mma16816(C[j1], ah, bh[2], bh[3]);
      mma16816(C[j0], al, bh[0], bh[1]);
      mma16816(C[j1], al, bh[2], bh[3]);
      mma16816(C[j0], ah, bl[0], bl[1]);
      mma16816(C[j1], ah, bl[2], bl[3]);
    }
  }
}

// ---- kernel 0: x -> bf16 hi/lo (+ zero counters) ----
__global__ void cvtx_kernel(const float* __restrict__ x){
  if (blockIdx.x == 0 && threadIdx.x < Ee) g_cnt[threadIdx.x] = 0;
  int i = blockIdx.x*256 + threadIdx.x;
  float4 v = ((const float4*)x)[i];
  u32 h0, l0, h1, l1;
  cvt_hl(v.x, v.y, h0, l0);
  cvt_hl(v.z, v.w, h1, l1);
  ((uint2*)g_xh)[i] = make_uint2(h0, h1);
  ((uint2*)g_xl)[i] = make_uint2(l0, l1);
}

// ---- kernel 1: router ----
__global__ void router_kernel(const float* __restrict__ x, const float* __restrict__ gw){
  int t = blockIdx.x;
  __shared__ float xs[Dd];
  __shared__ float lg[Ee];
  for (int i = threadIdx.x; i < Dd/4; i += 64)
    ((float4*)xs)[i] = ((const float4*)(x + (size_t)t*Dd))[i];
  __syncthreads();
  const float* w = gw + (size_t)threadIdx.x * Dd;
  float acc = 0.f;
  #pragma unroll 4
  for (int d = 0; d < Dd; d += 4){
    float4 wv = *(const float4*)(w + d);
    acc += wv.x*xs[d] + wv.y*xs[d+1] + wv.z*xs[d+2] + wv.w*xs[d+3];
  }
  lg[threadIdx.x] = acc;
  __syncthreads();
  if (threadIdx.x == 0){
    float mx = lg[0];
    for (int i = 1; i < Ee; i++) mx = fmaxf(mx, lg[i]);
    for (int i = 0; i < Ee; i++) lg[i] = __expf(lg[i] - mx);
    float wsum = 0.f; int ids[KK]; float ws[KK];
    for (int k = 0; k < KK; k++){
      int bi = 0; float bv = -1.f;
      for (int i = 0; i < Ee; i++){ float v = lg[i]; if (v > bv){ bv = v; bi = i; } }
      ids[k] = bi; ws[k] = bv; lg[bi] = -2.f; wsum += bv;
    }
    float inv = 1.f / wsum;
    for (int k = 0; k < KK; k++){
      int p = t*KK + k;
      g_topw[p] = ws[k] * inv;
      int slot = atomicAdd(&g_cnt[ids[k]], 1);
      g_slot[ids[k]*Tt + slot] = p;
    }
  }
}

// ---- kernel 2: gate+up GEMM (cp.async.bulk pipeline) ----
// grid (Ee, 8). A rows 0-63 = gate f0.., 64-127 = up f0..; warps 0-3 gate, 4-7 up.
__global__ void __launch_bounds__(256,1) gateup_kernel(
    const float* __restrict__ wg, const float* __restrict__ wu){
  int e = blockIdx.x;
  int nt = g_cnt[e];
  if (nt == 0) return;
  int f0 = blockIdx.y * 64;
  extern __shared__ char dsm[];
  __shared__ int sp[64];
  __shared__ __align__(8) u64 s_mb[STG];
  int tid = threadIdx.x, wid = tid >> 5, lane = tid & 31;
  int gid = lane >> 2, tig = lane & 3;
  u32 sb = (u32)__cvta_generic_to_shared(dsm);
  float* ub = (float*)dsm;
  u32 mb0 = (u32)__cvta_generic_to_shared(s_mb);

  if (tid < STG)
    asm volatile("mbarrier.init.shared.b64 [%0], 1;" :: "r"(mb0 + tid*8) : "memory");
  __syncthreads();

  // per-thread bulk source: A row (tid<128), X hi row (128..191), X lo row (192..255)
  const float* aRow = 0;
  if (tid < 128)
    aRow = (tid < 64 ? wg + ((size_t)e*II + f0 + tid)*Dd
                     : wu + ((size_t)e*II + f0 + tid - 64)*Dd);
  int xr = tid & 63;
  u32 adst = (u32)tid*ARS;
  u32 xdst = A_SZ + (tid >= 192 ? X_SZ : 0) + (u32)xr*XRS;

  int gbase = 0;
  for (int n0 = 0; n0 < nt; n0 += 64){
    int ntile = min(64, nt - n0), nfr = (ntile + 7) >> 3;
    int jpairs = (nfr + 1) >> 1;
    __syncthreads();
    if (tid < 64) sp[tid] = g_slot[e*Tt + ((n0 + tid < nt) ? n0 + tid : n0)];
    __syncthreads();
    asm volatile("fence.proxy.async.shared::cta;" ::: "memory");
    const u16* xRow = (tid >= 192 ? g_xl : g_xh) + (size_t)(sp[xr] >> 2)*Dd;

    float C[8][4];
    #pragma unroll
    for (int j = 0; j < 8; j++){ C[j][0]=C[j][1]=C[j][2]=C[j][3]=0.f; }

    #pragma unroll
    for (int s = 0; s < STG-1; s++){
      int st8 = s;                       // gbase%4==0 -> stage = local chunk %4
      u32 st = sb + st8*STAGE;
      if (tid == 0) mb_expect(mb0 + st8*8, TXB);
      if (tid < 128) bulk_ld(st + adst, aRow + s*KC, 256, mb0 + st8*8);
      else           bulk_ld(st + xdst, xRow + s*KC, 128, mb0 + st8*8);
    }
    for (int c = 0; c < Dd/KC; c++){
      int st8 = c & 3;
      mb_wait(mb0 + st8*8, ((gbase + c) >> 2) & 1);
      consume(C, sb + st8*STAGE, wid, lane, jpairs);
      __syncthreads();
      int cn = c + STG - 1;
      if (cn < Dd/KC){
        int sn = cn & 3;
        u32 st = sb + sn*STAGE;
        if (tid == 0) mb_expect(mb0 + sn*8, TXB);
        if (tid < 128) bulk_ld(st + adst, aRow + cn*KC, 256, mb0 + sn*8);
        else           bulk_ld(st + xdst, xRow + cn*KC, 128, mb0 + sn*8);
      }
    }
    gbase += Dd/KC;

    __syncthreads();
    if (wid >= 4){
      #pragma unroll
      for (int j = 0; j < 8; j++) if (j < nfr)
        #pragma unroll
        for (int q = 0; q < 4; q++){
          int row = (wid-4)*16 + gid + ((q>>1)<<3);
          int col = j*8 + tig*2 + (q&1);
          ub[row*USTR + col] = C[j][q];
        }
    }
    __syncthreads();
    if (wid < 4){
      #pragma unroll
      for (int j = 0; j < 8; j++) if (j < nfr)
        #pragma unroll
        for (int q = 0; q < 4; q++){
          int cc = j*8 + tig*2 + (q&1);
          if (cc < ntile){
            int rl = wid*16 + gid + ((q>>1)<<3);
            float g = C[j][q], u = ub[rl*USTR + cc];
            float h = (g / (1.f + __expf(-g))) * u;
            u16 hs; asm("cvt.rn.bf16.f32 %0, %1;" : "=h"(hs) : "f"(h));
            float lo = h - __uint_as_float(((u32)hs) << 16);
            u16 ls; asm("cvt.rn.bf16.f32 %0, %1;" : "=h"(ls) : "f"(lo));
            size_t idx = (size_t)sp[cc]*II + f0 + rl;
            g_Hh[idx] = hs;
            g_Hl[idx] = ls;
          }
        }
    }
    __syncthreads();
  }
}

// ---- kernel 3: down GEMM (cp.async.bulk pipeline) ----
// grid (Ee, 8): 128 d-rows per block, K=512.
__global__ void __launch_bounds__(256,1) down_kernel(const float* __restrict__ wd){
  int e = blockIdx.x;
  int nt = g_cnt[e];
  if (nt == 0) return;
  int d0 = blockIdx.y * 128;
  extern __shared__ char dsm[];
  __shared__ int sp[64];
  __shared__ __align__(8) u64 s_mb[STG];
  int tid = threadIdx.x, wid = tid >> 5, lane = tid & 31;
  int gid = lane >> 2, tig = lane & 3;
  u32 sb = (u32)__cvta_generic_to_shared(dsm);
  u32 mb0 = (u32)__cvta_generic_to_shared(s_mb);

  if (tid < STG)
    asm volatile("mbarrier.init.shared.b64 [%0], 1;" :: "r"(mb0 + tid*8) : "memory");
  __syncthreads();

  const float* aRow = (tid < 128) ? wd + ((size_t)e*Dd + d0 + tid)*II : 0;
  int xr = tid & 63;
  u32 adst = (u32)tid*ARS;
  u32 xdst = A_SZ + (tid >= 192 ? X_SZ : 0) + (u32)xr*XRS;

  int gbase = 0;
  for (int n0 = 0; n0 < nt; n0 += 64){
    int ntile = min(64, nt - n0), nfr = (ntile + 7) >> 3;
    int jpairs = (nfr + 1) >> 1;
    __syncthreads();
    if (tid < 64) sp[tid] = g_slot[e*Tt + ((n0 + tid < nt) ? n0 + tid : n0)];
    __syncthreads();
    asm volatile("fence.proxy.async.shared::cta;" ::: "memory");
    const u16* xRow = (tid >= 192 ? g_Hl : g_Hh) + (size_t)sp[xr]*II;

    float C[8][4];
    #pragma unroll
    for (int j = 0; j < 8; j++){ C[j][0]=C[j][1]=C[j][2]=C[j][3]=0.f; }

    #pragma unroll
    for (int s = 0; s < STG-1; s++){
      u32 st = sb + s*STAGE;
      if (tid == 0) mb_expect(mb0 + s*8, TXB);
      if (tid < 128) bulk_ld(st + adst, aRow + s*KC, 256, mb0 + s*8);
      else           bulk_ld(st + xdst, xRow + s*KC, 128, mb0 + s*8);
    }
    for (int c = 0; c < II/KC; c++){
      int st8 = c & 3;
      mb_wait(mb0 + st8*8, ((gbase + c) >> 2) & 1);
      consume(C, sb + st8*STAGE, wid, lane, jpairs);
      __syncthreads();
      int cn = c + STG - 1;
      if (cn < II/KC){
        int sn = cn & 3;
        u32 st = sb + sn*STAGE;
        if (tid == 0) mb_expect(mb0 + sn*8, TXB);
        if (tid < 128) bulk_ld(st + adst, aRow + cn*KC, 256, mb0 + sn*8);
        else           bulk_ld(st + xdst, xRow + cn*KC, 128, mb0 + sn*8);
      }
    }
    gbase += II/KC;

    int drow = d0 + wid*16 + gid;
    #pragma unroll
    for (int j = 0; j < 8; j++) if (j < nfr)
      #pragma unroll
      for (int q = 0; q < 4; q++){
        int cc = j*8 + tig*2 + (q&1);
        if (cc < ntile)
          g_Y[(size_t)sp[cc]*Dd + drow + ((q>>1)<<3)] = C[j][q];
      }
  }
}

// ---- kernel 4: combine ----
__global__ void combine_kernel(float* __restrict__ out){
  int t = blockIdx.x;
  int i = threadIdx.x;
  float w0 = g_topw[t*4+0], w1 = g_topw[t*4+1];
  float w2 = g_topw[t*4+2], w3 = g_topw[t*4+3];
  const float4* y0 = (const float4*)(g_Y + (size_t)(t*4+0)*Dd);
  const float4* y1 = (const float4*)(g_Y + (size_t)(t*4+1)*Dd);
  const float4* y2 = (const float4*)(g_Y + (size_t)(t*4+2)*Dd);
  const float4* y3 = (const float4*)(g_Y + (size_t)(t*4+3)*Dd);
  float4 a = y0[i], b = y1[i], c = y2[i], d = y3[i];
  float4 r;
  r.x = w0*a.x + w1*b.x + w2*c.x + w3*d.x;
  r.y = w0*a.y + w1*b.y + w2*c.y + w3*d.y;
  r.z = w0*a.z + w1*b.z + w2*c.z + w3*d.z;
  r.w = w0*a.w + w1*b.w + w2*c.w + w3*d.w;
  ((float4*)(out + (size_t)t*Dd))[i] = r;
}

extern "C" void kernel_launch(void* const* d_in, const int* in_sizes, int n_in,
                              void* d_out, int out_size){
  const float* x  = (const float*)d_in[0];
  const float* gw = (const float*)d_in[1];
  const float* wg = (const float*)d_in[2];
  const float* wu = (const float*)d_in[3];
  const float* wd = (const float*)d_in[4];
  float* out = (float*)d_out;
  (void)in_sizes; (void)n_in; (void)out_size;

  static int inited = 0;
  if (!inited){
    cudaFuncSetAttribute(gateup_kernel, cudaFuncAttributeMaxDynamicSharedMemorySize, SMEMT);
    cudaFuncSetAttribute(down_kernel,   cudaFuncAttributeMaxDynamicSharedMemorySize, SMEMT);
    inited = 1;
  }

  cvtx_kernel<<<Tt, 256>>>(x);
  router_kernel<<<Tt, 64>>>(x, gw);
  gateup_kernel<<<dim3(Ee, 8), 256, SMEMT>>>(wg, wu);
  down_kernel<<<dim3(Ee, 8), 256, SMEMT>>>(wd);
  combine_kernel<<<Tt, 256>>>(out);
}

// round 15
// speedup vs baseline: 1.2121x; 1.2121x over previous
#include <cuda_runtime.h>

#define Tt 512
#define Dd 1024
#define Ee 64
#define II 512
#define KK 4
#define NPAIR (Tt*KK)

typedef unsigned u32;
typedef unsigned short u16;

// ---- scratch ----
__device__ int   g_cnt[Ee];
__device__ int   g_slot[Ee*Tt];
__device__ float g_topw[NPAIR];
__device__ u16   g_xh[Tt*Dd];            // x as bf16 hi
__device__ u16   g_xl[Tt*Dd];            // x residual lo
__device__ u16   g_Hh[NPAIR*II];         // H bf16 hi
__device__ u16   g_Hl[NPAIR*II];         // H residual lo
__device__ float g_Y[NPAIR*Dd];          // 8 MB

// ---- pipeline geometry ----
#define KC 32                 // k per chunk
#define STG 4
#define AST4 144              // A row stride bytes (fp32, 32 floats + pad)
#define ASZ4 (128*AST4)       // 18432
#define XSTB 80               // X row stride bytes (bf16, 64B data + pad)
#define XSZB (64*XSTB)        // 5120
#define STAGE_SZ (ASZ4 + 2*XSZB)   // 28672
#define SMEM_TOT (STG*STAGE_SZ)    // 114688
#define USTR 65

__device__ __forceinline__ void cvt_hl(float vx, float vy, u32& h, u32& l){
  asm("cvt.rn.bf16x2.f32 %0, %1, %2;" : "=r"(h) : "f"(vy), "f"(vx));
  float r0 = vx - __uint_as_float(h << 16);
  float r1 = vy - __uint_as_float(h & 0xFFFF0000u);
  asm("cvt.rn.bf16x2.f32 %0, %1, %2;" : "=r"(l) : "f"(r1), "f"(r0));
}

__device__ __forceinline__ void mma16816(float* c, const u32* a, u32 b0, u32 b1){
  asm volatile(
    "mma.sync.aligned.m16n8k16.row.col.f32.bf16.bf16.f32 "
    "{%0,%1,%2,%3}, {%4,%5,%6,%7}, {%8,%9}, {%0,%1,%2,%3};"
    : "+f"(c[0]), "+f"(c[1]), "+f"(c[2]), "+f"(c[3])
    : "r"(a[0]), "r"(a[1]), "r"(a[2]), "r"(a[3]), "r"(b0), "r"(b1));
}

__device__ __forceinline__ void ldsm4(u32* r, u32 addr){
  asm volatile("ldmatrix.sync.aligned.m8n8.x4.shared.b16 {%0,%1,%2,%3}, [%4];"
    : "=r"(r[0]), "=r"(r[1]), "=r"(r[2]), "=r"(r[3]) : "r"(addr));
}

__device__ __forceinline__ float2 lds64f(u32 a){
  float2 v; asm volatile("ld.shared.v2.f32 {%0,%1}, [%2];" : "=f"(v.x), "=f"(v.y) : "r"(a));
  return v;
}

__device__ __forceinline__ void cpa16(u32 dst, const void* src){
  asm volatile("cp.async.cg.shared.global [%0], [%1], 16;" :: "r"(dst), "l"(src));
}
__device__ __forceinline__ void pfL2(const void* p){
  asm volatile("prefetch.global.L2 [%0];" :: "l"(p));
}
#define CPA_COMMIT asm volatile("cp.async.commit_group;" ::: "memory")
#define CPA_WAIT   asm volatile("cp.async.wait_group 2;" ::: "memory")

// build A fragment pair (hi/lo) from fp32 smem tile
__device__ __forceinline__ void afrag(u32 Ast, int wid, int lane, int ks, u32* ah, u32* al){
  int gid = lane >> 2, tig = lane & 3;
  u32 a0 = Ast + (u32)(wid*16 + gid)*AST4 + (u32)(ks*16 + tig*2)*4;
  float2 v00 = lds64f(a0);
  float2 v10 = lds64f(a0 + 8*AST4);
  float2 v01 = lds64f(a0 + 32);
  float2 v11 = lds64f(a0 + 8*AST4 + 32);
  cvt_hl(v00.x, v00.y, ah[0], al[0]);
  cvt_hl(v10.x, v10.y, ah[1], al[1]);
  cvt_hl(v01.x, v01.y, ah[2], al[2]);
  cvt_hl(v11.x, v11.y, ah[3], al[3]);
}

// consume one staged chunk: 2 k16 steps, jpairs n-pairs
__device__ __forceinline__ void consume(float C[8][4], u32 stg, int wid, int lane, int jpairs){
  u32 Ast = stg, Xh = stg + ASZ4, Xl = Xh + XSZB;
  int q = lane >> 3, rr = lane & 7;
  u32 bbase = (u32)(((q >> 1) << 3) + rr)*XSTB + (q & 1)*16;
  #pragma unroll
  for (int ks = 0; ks < 2; ks++){
    u32 ah[4], al[4];
    afrag(Ast, wid, lane, ks, ah, al);
    #pragma unroll
    for (int jp = 0; jp < 4; jp++){
      if (jp >= jpairs) break;
      u32 bh[4], bl[4];
      ldsm4(bh, Xh + bbase + (u32)(jp*16)*XSTB + ks*32);
      ldsm4(bl, Xl + bbase + (u32)(jp*16)*XSTB + ks*32);
      int j0 = jp*2, j1 = jp*2 + 1;
      mma16816(C[j0], ah, bh[0], bh[1]);
      mma16816(C[j1], ah, bh[2], bh[3]);
      mma16816(C[j0], al, bh[0], bh[1]);
      mma16816(C[j1], al, bh[2], bh[3]);
      mma16816(C[j0], ah, bl[0], bl[1]);
      mma16816(C[j1], ah, bl[2], bl[3]);
    }
  }
}

// ---- kernel 0: x -> bf16 hi/lo (+ zero counters) ----
__global__ void cvtx_kernel(const float* __restrict__ x){
  if (blockIdx.x == 0 && threadIdx.x < Ee) g_cnt[threadIdx.x] = 0;
  int i = blockIdx.x*256 + threadIdx.x;
  float4 v = ((const float4*)x)[i];
  u32 h0, l0, h1, l1;
  cvt_hl(v.x, v.y, h0, l0);
  cvt_hl(v.z, v.w, h1, l1);
  ((uint2*)g_xh)[i] = make_uint2(h0, h1);
  ((uint2*)g_xl)[i] = make_uint2(l0, l1);
}

// ---- kernel 1: router ----
__global__ void router_kernel(const float* __restrict__ x, const float* __restrict__ gw){
  int t = blockIdx.x;
  __shared__ float xs[Dd];
  __shared__ float lg[Ee];
  for (int i = threadIdx.x; i < Dd/4; i += 64)
    ((float4*)xs)[i] = ((const float4*)(x + (size_t)t*Dd))[i];
  __syncthreads();
  const float* w = gw + (size_t)threadIdx.x * Dd;
  float acc = 0.f;
  #pragma unroll 4
  for (int d = 0; d < Dd; d += 4){
    float4 wv = *(const float4*)(w + d);
    acc += wv.x*xs[d] + wv.y*xs[d+1] + wv.z*xs[d+2] + wv.w*xs[d+3];
  }
  lg[threadIdx.x] = acc;
  __syncthreads();
  if (threadIdx.x == 0){
    float mx = lg[0];
    for (int i = 1; i < Ee; i++) mx = fmaxf(mx, lg[i]);
    for (int i = 0; i < Ee; i++) lg[i] = __expf(lg[i] - mx);
    float wsum = 0.f; int ids[KK]; float ws[KK];
    for (int k = 0; k < KK; k++){
      int bi = 0; float bv = -1.f;
      for (int i = 0; i < Ee; i++){ float v = lg[i]; if (v > bv){ bv = v; bi = i; } }
      ids[k] = bi; ws[k] = bv; lg[bi] = -2.f; wsum += bv;
    }
    float inv = 1.f / wsum;
    for (int k = 0; k < KK; k++){
      int p = t*KK + k;
      g_topw[p] = ws[k] * inv;
      int slot = atomicAdd(&g_cnt[ids[k]], 1);
      g_slot[ids[k]*Tt + slot] = p;
    }
  }
}

// ---- kernel 2: gate+up GEMM (cp.async pipeline + L2 prefetch) ----
__global__ void __launch_bounds__(256,2) gateup_kernel(
    const float* __restrict__ wg, const float* __restrict__ wu){
  int e = blockIdx.x;
  int nt = g_cnt[e];
  if (nt == 0) return;
  int f0 = blockIdx.y * 64;
  extern __shared__ char dsm[];
  __shared__ int sp[64];
  int tid = threadIdx.x, wid = tid >> 5, lane = tid & 31;
  int gid = lane >> 2, tig = lane & 3;
  u32 sb = (u32)__cvta_generic_to_shared(dsm);
  float* ub = (float*)dsm;

  int r0 = tid >> 3, seg = tid & 7;
  const float* ap[4];
  ap[0] = wg + ((size_t)e*II + f0 + r0)*Dd + seg*4;
  ap[1] = ap[0] + (size_t)32*Dd;
  ap[2] = wu + ((size_t)e*II + f0 + r0)*Dd + seg*4;
  ap[3] = ap[2] + (size_t)32*Dd;
  u32 adst[4];
  #pragma unroll
  for (int j = 0; j < 4; j++) adst[j] = (u32)(j*32 + r0)*AST4 + (u32)seg*16;

  int xrow = tid >> 2, xseg = tid & 3;
  u32 xdst = (u32)xrow*XSTB + (u32)xseg*16;
  const int NCH = Dd/KC;

  for (int n0 = 0; n0 < nt; n0 += 64){
    int ntile = min(64, nt - n0), nfr = (ntile + 7) >> 3;
    int jpairs = (nfr + 1) >> 1;
    __syncthreads();
    if (tid < 64) sp[tid] = g_slot[e*Tt + ((n0 + tid < nt) ? n0 + tid : n0)];
    __syncthreads();
    const u16* xhPtr = g_xh + (size_t)(sp[xrow] >> 2)*Dd + xseg*8;
    const u16* xlPtr = g_xl + (size_t)(sp[xrow] >> 2)*Dd + xseg*8;

    float C[8][4];
    #pragma unroll
    for (int j = 0; j < 8; j++){ C[j][0]=C[j][1]=C[j][2]=C[j][3]=0.f; }

    #pragma unroll
    for (int s = 0; s < STG-1; s++){
      u32 st = sb + s*STAGE_SZ;
      #pragma unroll
      for (int j = 0; j < 4; j++) cpa16(st + adst[j], ap[j] + s*KC);
      cpa16(st + ASZ4 + xdst,        xhPtr + s*KC);
      cpa16(st + ASZ4 + XSZB + xdst, xlPtr + s*KC);
      CPA_COMMIT;
      // prologue prefetch: chunks STG-1+s
      int cp = STG - 1 + s;
      if (cp < NCH){
        if (seg == 0){
          #pragma unroll
          for (int j = 0; j < 4; j++) pfL2(ap[j] + cp*KC);
        }
        if (xseg == 0){ pfL2(xhPtr + cp*KC); pfL2(xlPtr + cp*KC); }
      }
    }
    for (int c = 0; c < NCH; c++){
      CPA_WAIT;
      __syncthreads();
      int cn = c + STG - 1;
      if (cn < NCH){
        u32 st = sb + (cn % STG)*STAGE_SZ;
        #pragma unroll
        for (int j = 0; j < 4; j++) cpa16(st + adst[j], ap[j] + cn*KC);
        cpa16(st + ASZ4 + xdst,        xhPtr + cn*KC);
        cpa16(st + ASZ4 + XSZB + xdst, xlPtr + cn*KC);
        int cp = cn + 2;
        if (cp < NCH){
          if (seg == 0){
            #pragma unroll
            for (int j = 0; j < 4; j++) pfL2(ap[j] + cp*KC);
          }
          if (xseg == 0){ pfL2(xhPtr + cp*KC); pfL2(xlPtr + cp*KC); }
        }
      }
      CPA_COMMIT;
      consume(C, sb + (c % STG)*STAGE_SZ, wid, lane, jpairs);
    }

    __syncthreads();
    if (wid >= 4){
      #pragma unroll
      for (int j = 0; j < 8; j++) if (j < nfr)
        #pragma unroll
        for (int q = 0; q < 4; q++){
          int row = (wid-4)*16 + gid + ((q>>1)<<3);
          int col = j*8 + tig*2 + (q&1);
          ub[row*USTR + col] = C[j][q];
        }
    }
    __syncthreads();
    if (wid < 4){
      #pragma unroll
      for (int j = 0; j < 8; j++) if (j < nfr)
        #pragma unroll
        for (int q = 0; q < 4; q++){
          int cc = j*8 + tig*2 + (q&1);
          if (cc < ntile){
            int rl = wid*16 + gid + ((q>>1)<<3);
            float g = C[j][q], u = ub[rl*USTR + cc];
            float h = (g / (1.f + __expf(-g))) * u;
            u16 hs; asm("cvt.rn.bf16.f32 %0, %1;" : "=h"(hs) : "f"(h));
            float lo = h - __uint_as_float(((u32)hs) << 16);
            u16 ls; asm("cvt.rn.bf16.f32 %0, %1;" : "=h"(ls) : "f"(lo));
            size_t idx = (size_t)sp[cc]*II + f0 + rl;
            g_Hh[idx] = hs;
            g_Hl[idx] = ls;
          }
        }
    }
    __syncthreads();
  }
}

// ---- kernel 3: down GEMM (cp.async pipeline + L2 prefetch) ----
__global__ void __launch_bounds__(256,2) down_kernel(const float* __restrict__ wd){
  int e = blockIdx.x;
  int nt = g_cnt[e];
  if (nt == 0) return;
  int d0 = blockIdx.y * 128;
  extern __shared__ char dsm[];
  __shared__ int sp[64];
  int tid = threadIdx.x, wid = tid >> 5, lane = tid & 31;
  int gid = lane >> 2, tig = lane & 3;
  u32 sb = (u32)__cvta_generic_to_shared(dsm);

  int r0 = tid >> 3, seg = tid & 7;
  const float* ap[4];
  u32 adst[4];
  #pragma unroll
  for (int j = 0; j < 4; j++){
    ap[j] = wd + ((size_t)e*Dd + d0 + j*32 + r0)*II + seg*4;
    adst[j] = (u32)(j*32 + r0)*AST4 + (u32)seg*16;
  }
  int xrow = tid >> 2, xseg = tid & 3;
  u32 xdst = (u32)xrow*XSTB + (u32)xseg*16;
  const int NCH = II/KC;

  for (int n0 = 0; n0 < nt; n0 += 64){
    int ntile = min(64, nt - n0), nfr = (ntile + 7) >> 3;
    int jpairs = (nfr + 1) >> 1;
    __syncthreads();
    if (tid < 64) sp[tid] = g_slot[e*Tt + ((n0 + tid < nt) ? n0 + tid : n0)];
    __syncthreads();
    const u16* xhPtr = g_Hh + (size_t)sp[xrow]*II + xseg*8;
    const u16* xlPtr = g_Hl + (size_t)sp[xrow]*II + xseg*8;

    float C[8][4];
    #pragma unroll
    for (int j = 0; j < 8; j++){ C[j][0]=C[j][1]=C[j][2]=C[j][3]=0.f; }

    #pragma unroll
    for (int s = 0; s < STG-1; s++){
      u32 st = sb + s*STAGE_SZ;
      #pragma unroll
      for (int j = 0; j < 4; j++) cpa16(st + adst[j], ap[j] + s*KC);
      cpa16(st + ASZ4 + xdst,        xhPtr + s*KC);
      cpa16(st + ASZ4 + XSZB + xdst, xlPtr + s*KC);
      CPA_COMMIT;
      int cp = STG - 1 + s;
      if (cp < NCH){
        if (seg == 0){
          #pragma unroll
          for (int j = 0; j < 4; j++) pfL2(ap[j] + cp*KC);
        }
        if (xseg == 0){ pfL2(xhPtr + cp*KC); pfL2(xlPtr + cp*KC); }
      }
    }
    for (int c = 0; c < NCH; c++){
      CPA_WAIT;
      __syncthreads();
      int cn = c + STG - 1;
      if (cn < NCH){
        u32 st = sb + (cn % STG)*STAGE_SZ;
        #pragma unroll
        for (int j = 0; j < 4; j++) cpa16(st + adst[j], ap[j] + cn*KC);
        cpa16(st + ASZ4 + xdst,        xhPtr + cn*KC);
        cpa16(st + ASZ4 + XSZB + xdst, xlPtr + cn*KC);
        int cp = cn + 2;
        if (cp < NCH){
          if (seg == 0){
            #pragma unroll
            for (int j = 0; j < 4; j++) pfL2(ap[j] + cp*KC);
          }
          if (xseg == 0){ pfL2(xhPtr + cp*KC); pfL2(xlPtr + cp*KC); }
        }
      }
      CPA_COMMIT;
      consume(C, sb + (c % STG)*STAGE_SZ, wid, lane, jpairs);
    }

    int drow = d0 + wid*16 + gid;
    #pragma unroll
    for (int j = 0; j < 8; j++) if (j < nfr)
      #pragma unroll
      for (int q = 0; q < 4; q++){
        int cc = j*8 + tig*2 + (q&1);
        if (cc < ntile)
          g_Y[(size_t)sp[cc]*Dd + drow + ((q>>1)<<3)] = C[j][q];
      }
  }
}

// ---- kernel 4: combine ----
__global__ void combine_kernel(float* __restrict__ out){
  int t = blockIdx.x;
  int i = threadIdx.x;
  float w0 = g_topw[t*4+0], w1 = g_topw[t*4+1];
  float w2 = g_topw[t*4+2], w3 = g_topw[t*4+3];
  const float4* y0 = (const float4*)(g_Y + (size_t)(t*4+0)*Dd);
  const float4* y1 = (const float4*)(g_Y + (size_t)(t*4+1)*Dd);
  const float4* y2 = (const float4*)(g_Y + (size_t)(t*4+2)*Dd);
  const float4* y3 = (const float4*)(g_Y + (size_t)(t*4+3)*Dd);
  float4 a = y0[i], b = y1[i], c = y2[i], d = y3[i];
  float4 r;
  r.x = w0*a.x + w1*b.x + w2*c.x + w3*d.x;
  r.y = w0*a.y + w1*b.y + w2*c.y + w3*d.y;
  r.z = w0*a.z + w1*b.z + w2*c.z + w3*d.z;
  r.w = w0*a.w + w1*b.w + w2*c.w + w3*d.w;
  ((float4*)(out + (size_t)t*Dd))[i] = r;
}

extern "C" void kernel_launch(void* const* d_in, const int* in_sizes, int n_in,
                              void* d_out, int out_size){
  const float* x  = (const float*)d_in[0];
  const float* gw = (const float*)d_in[1];
  const float* wg = (const float*)d_in[2];
  const float* wu = (const float*)d_in[3];
  const float* wd = (const float*)d_in[4];
  float* out = (float*)d_out;
  (void)in_sizes; (void)n_in; (void)out_size;

  static int inited = 0;
  if (!inited){
    cudaFuncSetAttribute(gateup_kernel, cudaFuncAttributeMaxDynamicSharedMemorySize, SMEM_TOT);
    cudaFuncSetAttribute(down_kernel,   cudaFuncAttributeMaxDynamicSharedMemorySize, SMEM_TOT);
    inited = 1;
  }

  cvtx_kernel<<<Tt, 256>>>(x);
  router_kernel<<<Tt, 64>>>(x, gw);
  gateup_kernel<<<dim3(Ee, 8), 256, SMEM_TOT>>>(wg, wu);
  down_kernel<<<dim3(Ee, 8), 256, SMEM_TOT>>>(wd);
  combine_kernel<<<Tt, 256>>>(out);
}